// round 1
// baseline (speedup 1.0000x reference)
#include <cuda_runtime.h>

// QPSolver: N=32, M=64, BS=512, ITERS=1000, ALPHA=BETA=1
// Out layout (float32): Xs (512,1001,128) then primal_sols (512,1001,32), C-order concat.

#define BSZ   512
#define NDIM  32
#define MDIM  64
#define ITERS 1000

__device__ float gD[MDIM * MDIM];      // D = H P^-1 H^T, row-major
__device__ float gHinv[NDIM * MDIM];   // pinv(H) = (H^T H)^-1 H^T, row-major (32x64)
__device__ float gWq[NDIM * MDIM];     // P^-1 H^T (32x64)
__device__ float gC;                   // 1/lambda_max(D)

// ---------------------------------------------------------------------------
// Gauss-Jordan with partial pivoting on an n x w augmented matrix in shared.
// Called by all threads of the block.
// ---------------------------------------------------------------------------
__device__ void gj_solve(float* A, int n, int w) {
    int t = threadIdx.x, NT = blockDim.x;
    __shared__ float fvec[32];
    __shared__ int spiv;
    for (int col = 0; col < n; col++) {
        if (t == 0) {
            int best = col; float bv = fabsf(A[col * w + col]);
            for (int r = col + 1; r < n; r++) {
                float v = fabsf(A[r * w + col]);
                if (v > bv) { bv = v; best = r; }
            }
            spiv = best;
        }
        __syncthreads();
        int p = spiv;
        if (p != col) {
            for (int j = t; j < w; j += NT) {
                float tmp = A[col * w + j]; A[col * w + j] = A[p * w + j]; A[p * w + j] = tmp;
            }
        }
        __syncthreads();
        float d = A[col * w + col];
        __syncthreads();
        float inv = 1.0f / d;
        for (int j = t; j < w; j += NT) A[col * w + j] *= inv;
        __syncthreads();
        if (t < n) fvec[t] = (t == col) ? 0.0f : A[t * w + col];
        __syncthreads();
        for (int i = t; i < n * w; i += NT) {
            int r = i / w;
            if (r != col) A[i] -= fvec[r] * A[col * w + (i - r * w)];
        }
        __syncthreads();
    }
}

// ---------------------------------------------------------------------------
// Setup kernel (1 block, 512 threads): Wq = P^-1 H^T, D = H Wq,
// Hinv = (H^T H)^-1 H^T, lambda_max(D) via 5 scaled squarings + power iter.
// ---------------------------------------------------------------------------
__global__ void setup_kernel(const float* __restrict__ P, const float* __restrict__ H) {
    __shared__ float sm[11264];
    float* sH   = sm;          // 2048 floats  (H, 64x32)
    float* sAug = sm + 2048;   // 3072 floats  (32x96 augmented)
    float* sWq  = sm + 5120;   // 2048 floats
    float* sD   = sm + 7168;   // 4096 floats
    float* sTmp = sm;          // 4096 floats (reuses sH+part of sAug, both dead by then)
    __shared__ float sV[64], sW[64];
    __shared__ double sT[8];

    int t = threadIdx.x, NT = blockDim.x;

    for (int i = t; i < 64 * 32; i += NT) sH[i] = H[i];
    __syncthreads();

    // --- solve P * Wq = H^T ---
    for (int i = t; i < 32 * 96; i += NT) {
        int r = i / 96, cI = i % 96;
        sAug[i] = (cI < 32) ? P[r * 32 + cI] : sH[(cI - 32) * 32 + r];
    }
    __syncthreads();
    gj_solve(sAug, 32, 96);
    for (int i = t; i < 32 * 64; i += NT) {
        float v = sAug[(i >> 6) * 96 + 32 + (i & 63)];
        sWq[i] = v; gWq[i] = v;
    }
    __syncthreads();

    // --- D = H * Wq (64x64) ---
    for (int i = t; i < 64 * 64; i += NT) {
        int r = i >> 6, cI = i & 63;
        float s = 0.0f;
        for (int k = 0; k < 32; k++) s = fmaf(sH[r * 32 + k], sWq[k * 64 + cI], s);
        sD[i] = s; gD[i] = s;
    }
    __syncthreads();

    // --- solve (H^T H) * Hinv = H^T ---
    for (int i = t; i < 32 * 96; i += NT) {
        int r = i / 96, cI = i % 96;
        float v;
        if (cI < 32) {
            float s = 0.0f;
            for (int k = 0; k < 64; k++) s = fmaf(sH[k * 32 + r], sH[k * 32 + cI], s);
            v = s;
        } else {
            v = sH[(cI - 32) * 32 + r];
        }
        sAug[i] = v;
    }
    __syncthreads();
    gj_solve(sAug, 32, 96);
    for (int i = t; i < 32 * 64; i += NT) gHinv[i] = sAug[(i >> 6) * 96 + 32 + (i & 63)];
    __syncthreads();

    // --- lambda_max: 5 trace-normalized squarings then power iteration ---
    if (t == 0) {
        double s = 0.0;
        for (int i = 0; i < 64; i++) s += (double)sD[i * 64 + i];
        sT[0] = s;
    }
    __syncthreads();
    {
        float inv = (float)(1.0 / sT[0]);
        for (int i = t; i < 4096; i += NT) sD[i] *= inv;
    }
    __syncthreads();
    const int NSQ = 5;
    for (int s = 1; s <= NSQ; s++) {
        for (int i = t; i < 4096; i += NT) {
            int r = i >> 6, cI = i & 63;
            float acc = 0.0f;
            for (int k = 0; k < 64; k++) acc = fmaf(sD[r * 64 + k], sD[k * 64 + cI], acc);
            sTmp[i] = acc;
        }
        __syncthreads();
        if (t == 0) {
            double tr = 0.0;
            for (int i = 0; i < 64; i++) tr += (double)sTmp[i * 64 + i];
            sT[s] = tr;
        }
        __syncthreads();
        float inv = (float)(1.0 / sT[s]);
        for (int i = t; i < 4096; i += NT) sD[i] = sTmp[i] * inv;
        __syncthreads();
    }
    if (t < 64) sV[t] = 1.0f + 0.001f * (float)t;
    __syncthreads();
    for (int it = 0; it < 48; it++) {
        if (t < 64) {
            float acc = 0.0f;
            for (int k = 0; k < 64; k++) acc = fmaf(sD[t * 64 + k], sV[k], acc);
            sW[t] = acc;
        }
        __syncthreads();
        if (t == 0) {
            float m = 0.0f;
            for (int i = 0; i < 64; i++) m = fmaxf(m, fabsf(sW[i]));
            sT[6] = (double)m;
        }
        __syncthreads();
        float inv = (float)(1.0 / sT[6]);
        if (t < 64) sV[t] = sW[t] * inv;
        __syncthreads();
    }
    if (t < 64) {
        float acc = 0.0f;
        for (int k = 0; k < 64; k++) acc = fmaf(sD[t * 64 + k], sV[k], acc);
        sW[t] = acc;
    }
    __syncthreads();
    if (t == 0) {
        double num = 0.0, den = 0.0;
        for (int i = 0; i < 64; i++) {
            num += (double)sV[i] * (double)sW[i];
            den += (double)sV[i] * (double)sV[i];
        }
        double lam = num / den;                  // lambda_1(C_NSQ)
        for (int s = NSQ; s >= 1; s--) lam = sqrt(sT[s] * lam);
        lam = sT[0] * lam;                       // lambda_1(D)
        gC = (float)(1.0 / lam);
    }
}

__device__ __forceinline__ float pairsum(unsigned long long v) {
    unsigned lo, hi;
    asm("mov.b64 {%0,%1},%2;" : "=r"(lo), "=r"(hi) : "l"(v));
    return __uint_as_float(lo) + __uint_as_float(hi);
}

// ---------------------------------------------------------------------------
// Main solver: warp-per-row, 1000 iterations fully in-warp.
// y' = c*(D y + z) + mu ;  z' = relu(y + z - 2 y') ;  p = Hinv z' - Hinv b
// ---------------------------------------------------------------------------
__global__ void __launch_bounds__(128, 1) solve_kernel(
    const float* __restrict__ q, const float* __restrict__ b, float* __restrict__ out)
{
    __shared__ __align__(16) float sy[4][64];
    __shared__ __align__(16) float sz[4][64];
    __shared__ __align__(16) float sHinv[32 * 68];   // pitch 68 (=4 mod 32): conflict-free

    int tid = threadIdx.x, lane = tid & 31, wid = tid >> 5;

    for (int i = tid; i < 32 * 64; i += 128)
        sHinv[(i >> 6) * 68 + (i & 63)] = gHinv[i];
    __syncthreads();

    int row = blockIdx.x * 4 + wid;
    float c = gC;

    // D rows (lane and lane+32) resident in registers, as packed f32x2 pairs.
    unsigned long long dA2[32], dB2[32];
    const unsigned long long* gD2 = (const unsigned long long*)gD;
#pragma unroll
    for (int i = 0; i < 32; i++) {
        dA2[i] = gD2[lane * 32 + i];
        dB2[i] = gD2[(lane + 32) * 32 + i];
    }

    // mu = c * (q Wq - b)
    const float* qr = q + row * NDIM;
    const float* br = b + (size_t)row * MDIM;
    float mu0 = 0.0f, mu1 = 0.0f;
#pragma unroll
    for (int i = 0; i < 32; i++) {
        float qi = qr[i];
        mu0 = fmaf(qi, gWq[i * 64 + lane], mu0);
        mu1 = fmaf(qi, gWq[i * 64 + lane + 32], mu1);
    }
    mu0 = c * (mu0 - br[lane]);
    mu1 = c * (mu1 - br[lane + 32]);

    // hb = Hinv[lane] . b_row
    float hb = 0.0f;
#pragma unroll
    for (int k = 0; k < 64; k++) hb = fmaf(sHinv[lane * 68 + k], br[k], hb);

    float* Xp = out + (size_t)row * (ITERS + 1) * 128;
    float* Pp = out + (size_t)BSZ * (ITERS + 1) * 128 + (size_t)row * (ITERS + 1) * 32;

    // k = 0 outputs
    Xp[lane] = 0.0f; Xp[lane + 32] = 0.0f; Xp[lane + 64] = 0.0f; Xp[lane + 96] = 0.0f;
    Pp[lane] = -hb;

    unsigned syb = (unsigned)__cvta_generic_to_shared(&sy[wid][0]);
    unsigned szb = (unsigned)__cvta_generic_to_shared(&sz[wid][0]);
    unsigned hvb = (unsigned)__cvta_generic_to_shared(&sHinv[0]) + (unsigned)lane * 272u;

    // init shared state to zero (asm stores to stay ordered with asm loads)
    asm volatile("st.shared.f32 [%0], %1;" :: "r"(syb + 4u * lane), "f"(0.0f));
    asm volatile("st.shared.f32 [%0], %1;" :: "r"(syb + 4u * (lane + 32)), "f"(0.0f));
    asm volatile("st.shared.f32 [%0], %1;" :: "r"(szb + 4u * lane), "f"(0.0f));
    asm volatile("st.shared.f32 [%0], %1;" :: "r"(szb + 4u * (lane + 32)), "f"(0.0f));
    __syncwarp();

    float y0 = 0.0f, y1 = 0.0f, z0 = 0.0f, z1 = 0.0f, p = -hb;
    bool conv = false;
    float* xk = Xp + 128;
    float* pk = Pp + 32;

    for (int k = 1; k <= ITERS; k++) {
        if (!conv) {
            // w = D y  (packed f32x2 FMAs, y broadcast from shared)
            unsigned long long a0 = 0ull, a1 = 0ull, c0 = 0ull, c1 = 0ull;
#pragma unroll
            for (int tq = 0; tq < 16; tq++) {
                unsigned long long yp0, yp1;
                asm volatile("ld.shared.v2.b64 {%0,%1},[%2];"
                             : "=l"(yp0), "=l"(yp1) : "r"(syb + 16u * tq));
                asm("fma.rn.f32x2 %0,%1,%2,%0;" : "+l"(a0) : "l"(dA2[2 * tq]),     "l"(yp0));
                asm("fma.rn.f32x2 %0,%1,%2,%0;" : "+l"(a1) : "l"(dA2[2 * tq + 1]), "l"(yp1));
                asm("fma.rn.f32x2 %0,%1,%2,%0;" : "+l"(c0) : "l"(dB2[2 * tq]),     "l"(yp0));
                asm("fma.rn.f32x2 %0,%1,%2,%0;" : "+l"(c1) : "l"(dB2[2 * tq + 1]), "l"(yp1));
            }
            float w0 = pairsum(a0) + pairsum(a1);
            float w1 = pairsum(c0) + pairsum(c1);

            float ny0 = fmaf(c, w0 + z0, mu0);
            float ny1 = fmaf(c, w1 + z1, mu1);
            float nz0 = fmaxf(fmaf(-2.0f, ny0, y0 + z0), 0.0f);
            float nz1 = fmaxf(fmaf(-2.0f, ny1, y1 + z1), 0.0f);

            bool same = (ny0 == y0) && (ny1 == y1) && (nz0 == z0) && (nz1 == z1);
            unsigned bl = __ballot_sync(0xffffffffu, same);   // also the warp barrier

            y0 = ny0; y1 = ny1; z0 = nz0; z1 = nz1;

            if (bl == 0xffffffffu) {
                conv = true;   // exact fixed point: all future iterates bit-identical
            } else {
                asm volatile("st.shared.f32 [%0], %1;" :: "r"(syb + 4u * lane),        "f"(y0));
                asm volatile("st.shared.f32 [%0], %1;" :: "r"(syb + 4u * (lane + 32)), "f"(y1));
                asm volatile("st.shared.f32 [%0], %1;" :: "r"(szb + 4u * lane),        "f"(z0));
                asm volatile("st.shared.f32 [%0], %1;" :: "r"(szb + 4u * (lane + 32)), "f"(z1));
                __syncwarp();
                // primal: p = Hinv[lane] . z' - hb
                unsigned long long p0 = 0ull, p1 = 0ull;
#pragma unroll
                for (int tq = 0; tq < 16; tq++) {
                    unsigned long long zp0, zp1, hp0, hp1;
                    asm volatile("ld.shared.v2.b64 {%0,%1},[%2];"
                                 : "=l"(zp0), "=l"(zp1) : "r"(szb + 16u * tq));
                    asm volatile("ld.shared.v2.b64 {%0,%1},[%2];"
                                 : "=l"(hp0), "=l"(hp1) : "r"(hvb + 16u * tq));
                    asm("fma.rn.f32x2 %0,%1,%2,%0;" : "+l"(p0) : "l"(hp0), "l"(zp0));
                    asm("fma.rn.f32x2 %0,%1,%2,%0;" : "+l"(p1) : "l"(hp1), "l"(zp1));
                }
                p = pairsum(p0) + pairsum(p1) - hb;
            }
        }
        xk[lane] = y0; xk[lane + 32] = y1; xk[lane + 64] = z0; xk[lane + 96] = z1;
        pk[lane] = p;
        xk += 128; pk += 32;
    }
}

extern "C" void kernel_launch(void* const* d_in, const int* in_sizes, int n_in,
                              void* d_out, int out_size) {
    // Identify inputs by element count (all distinct): q 16384, b 32768, P 1024, H 2048.
    const float *q = nullptr, *b = nullptr, *P = nullptr, *H = nullptr;
    for (int i = 0; i < n_in; i++) {
        switch (in_sizes[i]) {
            case BSZ * NDIM:  q = (const float*)d_in[i]; break;  // 16384
            case BSZ * MDIM:  b = (const float*)d_in[i]; break;  // 32768
            case NDIM * NDIM: P = (const float*)d_in[i]; break;  // 1024
            case MDIM * NDIM: H = (const float*)d_in[i]; break;  // 2048
            default: break;                                      // iters (1) ignored
        }
    }
    setup_kernel<<<1, 512>>>(P, H);
    solve_kernel<<<BSZ / 4, 128>>>(q, b, (float*)d_out);
}